// round 1
// baseline (speedup 1.0000x reference)
#include <cuda_runtime.h>

#define D       128   // feature dim
#define NPE     32    // neighbors per row (both seq and useq)
#define ROWS    32    // rows per block
#define THREADS 256

// Scratch for the intermediate edge features [E,128]; E=50000 -> 6.4M floats.
// Sized with headroom (8.39M floats = 33.5 MB).
__device__ float g_edge[8388608];
// 1 if index arrays are int64, 0 if int32 (runtime-detected).
__device__ int g_is64;

// Indices are random in [0, 100000). If stored as int64 (little-endian,
// non-negative < 2^31), every odd 32-bit word is 0. If int32, the odd words
// are themselves random indices and are ~never all zero across 1024 samples.
__global__ void detect_kernel(const unsigned* __restrict__ p, int npairs) {
    unsigned any = 0;
    for (int i = threadIdx.x; i < npairs; i += 32)
        any |= p[2 * i + 1];
    unsigned b = __ballot_sync(0xffffffffu, any != 0u);
    if (threadIdx.x == 0)
        g_is64 = (b == 0u) ? 1 : 0;
}

// Fused: dst[r] = (optional relu)( (masked-mean_j src[idx[r][j]]) @ W )
// Masked mean = softmax over {1, -9e15} logits -> uniform over idx>0 slots;
// if no slot has idx>0, weights are 1/32 (and all gathered rows are src[0]).
template <bool RELU, bool SRC_EDGE, bool DST_EDGE>
__global__ __launch_bounds__(THREADS)
void agg_gemm_kernel(const float* __restrict__ src_in,
                     const void*  __restrict__ idx_in,
                     const float* __restrict__ W,
                     float*       __restrict__ dst_in,
                     int nrows) {
    __shared__ float sA[ROWS][D];   // 16 KB aggregated rows

    const float* src = SRC_EDGE ? (const float*)g_edge : src_in;
    float*       dst = DST_EDGE ? (float*)g_edge       : dst_in;

    const int tid  = threadIdx.x;
    const int lane = tid & 31;
    const int warp = tid >> 5;
    const int row0 = blockIdx.x * ROWS;
    const int is64 = g_is64;

    // ---- Phase 1: gather + masked mean. One warp per row; lane owns 4 cols.
    for (int e = warp; e < ROWS; e += THREADS / 32) {
        const int r = row0 + e;
        float4 acc = make_float4(0.f, 0.f, 0.f, 0.f);
        if (r < nrows) {
            long long myidx;
            if (is64) myidx = ((const long long*)idx_in)[(long long)r * NPE + lane];
            else      myidx = (long long)((const int*)idx_in)[(long long)r * NPE + lane];
            const unsigned m = __ballot_sync(0xffffffffu, myidx > 0);
            const int k = __popc(m);
            const float scale = (k == 0) ? (1.0f / NPE) : (1.0f / (float)k);
            #pragma unroll 4
            for (int j = 0; j < NPE; ++j) {
                const long long ij = __shfl_sync(0xffffffffu, myidx, j);
                if (k == 0 || ij > 0) {
                    const float4 v = __ldg((const float4*)(src + ij * D) + lane);
                    acc.x += v.x; acc.y += v.y; acc.z += v.z; acc.w += v.w;
                }
            }
            acc.x *= scale; acc.y *= scale; acc.z *= scale; acc.w *= scale;
        }
        *(float4*)&sA[e][lane * 4] = acc;   // zeros for tail rows
    }
    __syncthreads();

    // ---- Phase 2: sA[32][128] @ W[128][128], 4x4 register tile per thread.
    // W streamed through __ldg (64 KB -> resident in L1 across CTAs).
    const int tx = tid & 31;     // column group: cols [4*tx, 4*tx+3]
    const int ty = tid >> 5;     // row group:    rows [4*ty, 4*ty+3]
    const int c0 = tx * 4;
    const int rl = ty * 4;
    float acc[4][4] = {};
    #pragma unroll 4
    for (int k = 0; k < D; ++k) {
        const float4 w4 = __ldg((const float4*)(W + k * D + c0));
        #pragma unroll
        for (int i = 0; i < 4; ++i) {
            const float a = sA[rl + i][k];   // warp-broadcast smem read
            acc[i][0] = fmaf(a, w4.x, acc[i][0]);
            acc[i][1] = fmaf(a, w4.y, acc[i][1]);
            acc[i][2] = fmaf(a, w4.z, acc[i][2]);
            acc[i][3] = fmaf(a, w4.w, acc[i][3]);
        }
    }
    #pragma unroll
    for (int i = 0; i < 4; ++i) {
        const int r = row0 + rl + i;
        if (r < nrows) {
            float4 o;
            o.x = acc[i][0]; o.y = acc[i][1]; o.z = acc[i][2]; o.w = acc[i][3];
            if (RELU) {
                o.x = fmaxf(o.x, 0.f); o.y = fmaxf(o.y, 0.f);
                o.z = fmaxf(o.z, 0.f); o.w = fmaxf(o.w, 0.f);
            }
            *(float4*)&dst[(long long)r * D + c0] = o;
        }
    }
}

// Inputs (metadata order):
// 0: x        [100000,128] f32
// 1: seq      [50000,32]   int   (int32 or int64, runtime-detected)
// 2: text2emb (unused)
// 3: useq     [50000,32]   int
// 4: data_idx (unused)
// 5: weight1  [128,128] f32
// 6: weight2  [128,128] f32
// 7: weight3  (unused)
extern "C" void kernel_launch(void* const* d_in, const int* in_sizes, int n_in,
                              void* d_out, int out_size) {
    const float* x    = (const float*)d_in[0];
    const void*  seq  = d_in[1];
    const void*  useq = d_in[3];
    const float* w1   = (const float*)d_in[5];
    const float* w2   = (const float*)d_in[6];
    float*       out  = (float*)d_out;

    const int E = in_sizes[1] / NPE;
    const int U = in_sizes[3] / NPE;

    detect_kernel<<<1, 32>>>((const unsigned*)seq, 1024);

    // Stage 1: edge = relu( (masked-mean x[seq]) @ W1 )  -> g_edge
    agg_gemm_kernel<true, false, true>
        <<<(E + ROWS - 1) / ROWS, THREADS>>>(x, seq, w1, nullptr, E);

    // Stage 2: out = (masked-mean edge[useq]) @ W2
    agg_gemm_kernel<false, true, false>
        <<<(U + ROWS - 1) / ROWS, THREADS>>>(nullptr, useq, w2, out, U);
}

// round 2
// speedup vs baseline: 1.2062x; 1.2062x over previous
#include <cuda_runtime.h>
#include <cuda_fp16.h>

#define D       128   // feature dim
#define NPE     32    // neighbors per row (both seq and useq)
#define ROWS    32    // rows per block
#define THREADS 256

// fp16 copy of x: up to 16M halfs (32 MB) -> covers N=100000 x 128.
__device__ __half g_xh[16777216];
// fp16 intermediate edge features [E,128]; headroom 8M halfs (16 MB).
__device__ __half g_edge_h[8388608];
// 1 if index arrays are int64, 0 if int32 (runtime-detected).
__device__ int g_is64;

// Prep: (a) detect index width (block 0, warp 0), (b) convert x fp32 -> fp16.
// Indices are non-negative < 2^31, so int64 storage => every odd 32-bit word
// is zero; int32 storage => odd words are random indices, ~never all zero.
__global__ void prep_kernel(const float* __restrict__ x, long long n4,
                            const unsigned* __restrict__ seqw, int npairs) {
    if (blockIdx.x == 0 && threadIdx.x < 32) {
        unsigned any = 0;
        for (int i = threadIdx.x; i < npairs; i += 32)
            any |= seqw[2 * i + 1];
        unsigned b = __ballot_sync(0xffffffffu, any != 0u);
        if (threadIdx.x == 0)
            g_is64 = (b == 0u) ? 1 : 0;
    }
    const long long stride = (long long)gridDim.x * blockDim.x;
    const float4* __restrict__ x4 = (const float4*)x;
    uint2* __restrict__ out = (uint2*)g_xh;
    for (long long i = (long long)blockIdx.x * blockDim.x + threadIdx.x;
         i < n4; i += stride) {
        const float4 v = __ldg(&x4[i]);
        uint2 o;
        *(__half2*)&o.x = __floats2half2_rn(v.x, v.y);
        *(__half2*)&o.y = __floats2half2_rn(v.z, v.w);
        out[i] = o;
    }
}

__device__ __forceinline__ unsigned long long pack2(float a, float b) {
    unsigned long long r;
    asm("mov.b64 %0, {%1, %2};" : "=l"(r) : "f"(a), "f"(b));
    return r;
}
__device__ __forceinline__ void unpack2(unsigned long long v, float& a, float& b) {
    asm("mov.b64 {%0, %1}, %2;" : "=f"(a), "=f"(b) : "l"(v));
}
__device__ __forceinline__ void ffma2(unsigned long long& acc,
                                      unsigned long long a,
                                      unsigned long long b) {
    asm("fma.rn.f32x2 %0, %1, %2, %0;" : "+l"(acc) : "l"(a), "l"(b));
}

// Fused: dst[r] = (optional relu)( (masked-mean_j src16[idx[r][j]]) @ W )
// Masked mean = softmax over {1,-9e15} = uniform over idx>0 slots;
// if no slot has idx>0, weights are all 1/NPE (rows are src[0]).
template <bool RELU, bool SRC_X, bool DST_HALF>
__global__ __launch_bounds__(THREADS)
void agg_gemm_kernel(const void* __restrict__ idx_in,
                     const float* __restrict__ W,
                     float* __restrict__ dst_f,
                     int nrows) {
    __shared__ float sA[ROWS][D];   // 16 KB aggregated rows (fp32)

    const __half* __restrict__ src = SRC_X ? g_xh : g_edge_h;

    const int tid  = threadIdx.x;
    const int lane = tid & 31;
    const int warp = tid >> 5;
    const int row0 = blockIdx.x * ROWS;
    const int is64 = g_is64;

    // ---- Phase 1: gather fp16 rows + masked mean (fp32 accumulate).
    // One warp per output row; lane owns 4 consecutive cols (8 B = uint2).
    for (int e = warp; e < ROWS; e += THREADS / 32) {
        const int r = row0 + e;
        float4 acc = make_float4(0.f, 0.f, 0.f, 0.f);
        if (r < nrows) {
            int myidx;
            if (is64) myidx = (int)((const long long*)idx_in)[(long long)r * NPE + lane];
            else      myidx = ((const int*)idx_in)[(long long)r * NPE + lane];
            const unsigned m = __ballot_sync(0xffffffffu, myidx > 0);
            const int k = __popc(m);
            const float scale = (k == 0) ? (1.0f / NPE) : (1.0f / (float)k);
            const bool all = (k == 0);
            #pragma unroll 4
            for (int j = 0; j < NPE; ++j) {
                const int ij = __shfl_sync(0xffffffffu, myidx, j);
                if (all || ij > 0) {
                    const uint2 v = __ldg((const uint2*)(src + (long long)ij * D) + lane);
                    const float2 f0 = __half22float2(*(const __half2*)&v.x);
                    const float2 f1 = __half22float2(*(const __half2*)&v.y);
                    acc.x += f0.x; acc.y += f0.y; acc.z += f1.x; acc.w += f1.y;
                }
            }
            acc.x *= scale; acc.y *= scale; acc.z *= scale; acc.w *= scale;
        }
        *(float4*)&sA[e][lane * 4] = acc;   // zeros for tail rows
    }
    __syncthreads();

    // ---- Phase 2: sA[32][128] @ W[128][128] with packed f32x2 FMA.
    // Thread tile: 4 rows x 4 cols; accumulators are column-pair u64s.
    const int tx = tid & 31;     // col group: cols [4*tx, 4*tx+3]
    const int ty = tid >> 5;     // row group: rows [4*ty, 4*ty+3]
    const int c0 = tx * 4;
    const int rl = ty * 4;
    unsigned long long acc01[4] = {0, 0, 0, 0};  // (c0, c0+1) for rows rl..rl+3
    unsigned long long acc23[4] = {0, 0, 0, 0};  // (c0+2, c0+3)
    #pragma unroll 4
    for (int k = 0; k < D; ++k) {
        const float4 w4 = __ldg((const float4*)(W + k * D + c0));
        const unsigned long long w01 = pack2(w4.x, w4.y);
        const unsigned long long w23 = pack2(w4.z, w4.w);
        #pragma unroll
        for (int i = 0; i < 4; ++i) {
            const float a = sA[rl + i][k];          // broadcast LDS.32
            const unsigned long long aa = pack2(a, a);
            ffma2(acc01[i], aa, w01);
            ffma2(acc23[i], aa, w23);
        }
    }
    #pragma unroll
    for (int i = 0; i < 4; ++i) {
        const int r = row0 + rl + i;
        if (r >= nrows) continue;
        float f0, f1, f2, f3;
        unpack2(acc01[i], f0, f1);
        unpack2(acc23[i], f2, f3);
        if (RELU) {
            f0 = fmaxf(f0, 0.f); f1 = fmaxf(f1, 0.f);
            f2 = fmaxf(f2, 0.f); f3 = fmaxf(f3, 0.f);
        }
        if (DST_HALF) {
            uint2 o;
            *(__half2*)&o.x = __floats2half2_rn(f0, f1);
            *(__half2*)&o.y = __floats2half2_rn(f2, f3);
            *(uint2*)(g_edge_h + (long long)r * D + c0) = o;
        } else {
            float4 o; o.x = f0; o.y = f1; o.z = f2; o.w = f3;
            *(float4*)(dst_f + (long long)r * D + c0) = o;
        }
    }
}

// Inputs (metadata order):
// 0: x [100000,128] f32   1: seq [50000,32] int   2: text2emb (unused)
// 3: useq [50000,32] int  4: data_idx (unused)    5: weight1 [128,128] f32
// 6: weight2 [128,128] f32  7: weight3 (unused)
extern "C" void kernel_launch(void* const* d_in, const int* in_sizes, int n_in,
                              void* d_out, int out_size) {
    const float* x    = (const float*)d_in[0];
    const void*  seq  = d_in[1];
    const void*  useq = d_in[3];
    const float* w1   = (const float*)d_in[5];
    const float* w2   = (const float*)d_in[6];
    float*       out  = (float*)d_out;

    const int E = in_sizes[1] / NPE;
    const int U = in_sizes[3] / NPE;
    const long long n4 = (long long)in_sizes[0] / 4;

    prep_kernel<<<1024, 256>>>(x, n4, (const unsigned*)seq, 1024);

    // Stage 1: edge_h = relu( (masked-mean x_h[seq]) @ W1 )  -> g_edge_h (fp16)
    agg_gemm_kernel<true, true, true>
        <<<(E + ROWS - 1) / ROWS, THREADS>>>(seq, w1, nullptr, E);

    // Stage 2: out = (masked-mean edge_h[useq]) @ W2  (fp32)
    agg_gemm_kernel<false, false, false>
        <<<(U + ROWS - 1) / ROWS, THREADS>>>(useq, w2, out, U);
}